// round 1
// baseline (speedup 1.0000x reference)
#include <cuda_runtime.h>
#include <math.h>

// Problem constants
#define BATCH 4
#define SEQ   4096
#define DIM   512
#define KEXP  8
#define ROWS  (BATCH*SEQ)        // 16384 token rows
#define CHUNK 128                // scan chunk length
#define NCHUNK (SEQ/CHUNK)       // 32 chunks
#define INV_TAU (1.0f/16.0f)
#define LN_EPS 1e-5f

// ---------------------------------------------------------------------------
// Scratch (static device globals; no allocation at runtime)
// ---------------------------------------------------------------------------
__device__ float g_i[ROWS * DIM];                       // 32 MB  : x @ W_i
__device__ float g_e[ROWS * KEXP];                      // 512 KB : x @ W_e
__device__ float g_s[ROWS * KEXP];                      // 512 KB : x @ W_s
__device__ float g_S[BATCH * NCHUNK * KEXP * DIM];      // 2 MB   : per-chunk local end states
__device__ float g_P[BATCH * NCHUNK * KEXP * DIM];      // 2 MB   : per-chunk start states (prefix)
__device__ float g_y[ROWS * DIM];                       // 32 MB  : scan output / LN in place

// ---------------------------------------------------------------------------
// SGEMM body: C[M x 512] = A[M x 512] * B[512 x 512], all row-major fp32.
// BM=128, BN=128, BK=8, 8x8 per thread, 256 threads.
// ---------------------------------------------------------------------------
__device__ __forceinline__ void sgemm_body(const float* __restrict__ A,
                                           const float* __restrict__ B,
                                           float* __restrict__ C) {
    __shared__ float As[8][132];   // [k][m], padded to kill store conflicts
    __shared__ float Bs[8][128];   // [k][n]

    const int tid = threadIdx.x;
    const int bx = blockIdx.x;           // N tile (0..3)
    const int by = blockIdx.y;           // M tile (0..127)
    const int row0 = by * 128;
    const int col0 = bx * 128;

    const int tx = tid & 15;             // 0..15 -> 8 output cols each
    const int ty = tid >> 4;             // 0..15 -> 8 output rows each

    const int aRow = tid >> 1;           // 0..127
    const int aK   = (tid & 1) * 4;      // 0 or 4
    const int bRow = tid >> 5;           // 0..7
    const int bCol = (tid & 31) * 4;     // 0..124

    float acc[8][8] = {};

    const float* Aptr = A + (size_t)(row0 + aRow) * DIM + aK;
    const float* Bptr = B + (size_t)bRow * DIM + col0 + bCol;

    for (int k0 = 0; k0 < DIM; k0 += 8) {
        float4 av = *(const float4*)(Aptr + k0);
        float4 bv = *(const float4*)(Bptr + (size_t)k0 * DIM);
        As[aK + 0][aRow] = av.x;
        As[aK + 1][aRow] = av.y;
        As[aK + 2][aRow] = av.z;
        As[aK + 3][aRow] = av.w;
        *(float4*)(&Bs[bRow][bCol]) = bv;
        __syncthreads();

        #pragma unroll
        for (int kk = 0; kk < 8; kk++) {
            float a[8], b[8];
            *(float4*)(a)     = *(const float4*)(&As[kk][ty * 8]);
            *(float4*)(a + 4) = *(const float4*)(&As[kk][ty * 8 + 4]);
            *(float4*)(b)     = *(const float4*)(&Bs[kk][tx * 8]);
            *(float4*)(b + 4) = *(const float4*)(&Bs[kk][tx * 8 + 4]);
            #pragma unroll
            for (int i = 0; i < 8; i++)
                #pragma unroll
                for (int j = 0; j < 8; j++)
                    acc[i][j] = fmaf(a[i], b[j], acc[i][j]);
        }
        __syncthreads();
    }

    #pragma unroll
    for (int i = 0; i < 8; i++) {
        float4 v0 = make_float4(acc[i][0], acc[i][1], acc[i][2], acc[i][3]);
        float4 v1 = make_float4(acc[i][4], acc[i][5], acc[i][6], acc[i][7]);
        float* crow = C + (size_t)(row0 + ty * 8 + i) * DIM + col0 + tx * 8;
        *(float4*)(crow)     = v0;
        *(float4*)(crow + 4) = v1;
    }
}

__global__ __launch_bounds__(256, 2) void sgemm1_kernel(const float* __restrict__ x,
                                                        const float* __restrict__ W_i) {
    sgemm_body(x, W_i, g_i);
}

__global__ __launch_bounds__(256, 2) void sgemm2_kernel(const float* __restrict__ W_out,
                                                        float* __restrict__ out) {
    sgemm_body(g_y, W_out, out);
}

// ---------------------------------------------------------------------------
// e = x @ W_e, s = x @ W_s   (one warp per token row; 16 dot products of 512)
// ---------------------------------------------------------------------------
__global__ __launch_bounds__(256) void es_kernel(const float* __restrict__ x,
                                                 const float* __restrict__ W_e,
                                                 const float* __restrict__ W_s) {
    const int row  = blockIdx.x * 8 + (threadIdx.x >> 5);
    const int lane = threadIdx.x & 31;
    const float* xr = x + (size_t)row * DIM;

    float acc[16];
    #pragma unroll
    for (int k = 0; k < 16; k++) acc[k] = 0.0f;

    for (int d = lane; d < DIM; d += 32) {
        float xv = xr[d];
        float4 w0 = *(const float4*)(W_e + d * KEXP);
        float4 w1 = *(const float4*)(W_e + d * KEXP + 4);
        float4 v0 = *(const float4*)(W_s + d * KEXP);
        float4 v1 = *(const float4*)(W_s + d * KEXP + 4);
        acc[0]  = fmaf(xv, w0.x, acc[0]);  acc[1]  = fmaf(xv, w0.y, acc[1]);
        acc[2]  = fmaf(xv, w0.z, acc[2]);  acc[3]  = fmaf(xv, w0.w, acc[3]);
        acc[4]  = fmaf(xv, w1.x, acc[4]);  acc[5]  = fmaf(xv, w1.y, acc[5]);
        acc[6]  = fmaf(xv, w1.z, acc[6]);  acc[7]  = fmaf(xv, w1.w, acc[7]);
        acc[8]  = fmaf(xv, v0.x, acc[8]);  acc[9]  = fmaf(xv, v0.y, acc[9]);
        acc[10] = fmaf(xv, v0.z, acc[10]); acc[11] = fmaf(xv, v0.w, acc[11]);
        acc[12] = fmaf(xv, v1.x, acc[12]); acc[13] = fmaf(xv, v1.y, acc[13]);
        acc[14] = fmaf(xv, v1.z, acc[14]); acc[15] = fmaf(xv, v1.w, acc[15]);
    }
    #pragma unroll
    for (int off = 16; off > 0; off >>= 1) {
        #pragma unroll
        for (int k = 0; k < 16; k++)
            acc[k] += __shfl_xor_sync(0xFFFFFFFFu, acc[k], off);
    }
    if (lane == 0) {
        #pragma unroll
        for (int k = 0; k < 8; k++) g_e[(size_t)row * KEXP + k] = acc[k];
        #pragma unroll
        for (int k = 0; k < 8; k++) g_s[(size_t)row * KEXP + k] = acc[8 + k];
    }
}

// ---------------------------------------------------------------------------
// Decay helper: o[k] = exp(logsigmoid(o_param[k,d]) / tau), per thread d.
// ---------------------------------------------------------------------------
__device__ __forceinline__ void load_decay(const float* __restrict__ o_param,
                                           int d, float scale, float o[KEXP]) {
    #pragma unroll
    for (int k = 0; k < KEXP; k++) {
        float op = o_param[k * DIM + d];
        float ls = fminf(op, 0.0f) - log1pf(expf(-fabsf(op)));
        o[k] = expf(ls * scale);
    }
}

// ---------------------------------------------------------------------------
// Scan phase 1: per-chunk local end state (starting from zero)
// grid (NCHUNK, BATCH), block DIM
// ---------------------------------------------------------------------------
__global__ __launch_bounds__(DIM) void scan_local_kernel(const float* __restrict__ o_param) {
    const int c = blockIdx.x, b = blockIdx.y, d = threadIdx.x;
    float o[KEXP], m[KEXP];
    load_decay(o_param, d, INV_TAU, o);
    #pragma unroll
    for (int k = 0; k < KEXP; k++) m[k] = 0.0f;

    const int t0 = c * CHUNK;
    const float* ip = g_i + ((size_t)b * SEQ + t0) * DIM + d;
    const float* ep = g_e + ((size_t)b * SEQ + t0) * KEXP;

    #pragma unroll 2
    for (int t = 0; t < CHUNK; t++) {
        float iv = ip[(size_t)t * DIM];
        float4 e0 = *(const float4*)(ep + t * KEXP);
        float4 e1 = *(const float4*)(ep + t * KEXP + 4);
        float ev[KEXP] = {e0.x, e0.y, e0.z, e0.w, e1.x, e1.y, e1.z, e1.w};
        #pragma unroll
        for (int k = 0; k < KEXP; k++)
            m[k] = fmaf(o[k], m[k], ev[k] * iv);
    }
    #pragma unroll
    for (int k = 0; k < KEXP; k++)
        g_S[(((size_t)b * NCHUNK + c) * KEXP + k) * DIM + d] = m[k];
}

// ---------------------------------------------------------------------------
// Scan phase 2: sequential prefix over chunks (cheap)
// grid BATCH, block DIM
// ---------------------------------------------------------------------------
__global__ __launch_bounds__(DIM) void scan_prefix_kernel(const float* __restrict__ o_param) {
    const int b = blockIdx.x, d = threadIdx.x;
    float oL[KEXP];
    load_decay(o_param, d, INV_TAU * (float)CHUNK, oL);   // o^CHUNK
    float p[KEXP];
    #pragma unroll
    for (int k = 0; k < KEXP; k++) p[k] = 0.0f;

    for (int c = 0; c < NCHUNK; c++) {
        #pragma unroll
        for (int k = 0; k < KEXP; k++)
            g_P[(((size_t)b * NCHUNK + c) * KEXP + k) * DIM + d] = p[k];
        if (c < NCHUNK - 1) {
            #pragma unroll
            for (int k = 0; k < KEXP; k++)
                p[k] = fmaf(oL[k], p[k],
                            g_S[(((size_t)b * NCHUNK + c) * KEXP + k) * DIM + d]);
        }
    }
}

// ---------------------------------------------------------------------------
// Scan phase 3: replay chunk from its prefix state, emit y
// grid (NCHUNK, BATCH), block DIM
// ---------------------------------------------------------------------------
__global__ __launch_bounds__(DIM) void scan_apply_kernel(const float* __restrict__ o_param) {
    const int c = blockIdx.x, b = blockIdx.y, d = threadIdx.x;
    float o[KEXP], m[KEXP];
    load_decay(o_param, d, INV_TAU, o);
    #pragma unroll
    for (int k = 0; k < KEXP; k++)
        m[k] = g_P[(((size_t)b * NCHUNK + c) * KEXP + k) * DIM + d];

    const int t0 = c * CHUNK;
    const float* ip = g_i + ((size_t)b * SEQ + t0) * DIM + d;
    const float* ep = g_e + ((size_t)b * SEQ + t0) * KEXP;
    const float* sp = g_s + ((size_t)b * SEQ + t0) * KEXP;
    float* yp = g_y + ((size_t)b * SEQ + t0) * DIM + d;

    #pragma unroll 2
    for (int t = 0; t < CHUNK; t++) {
        float iv = ip[(size_t)t * DIM];
        float4 e0 = *(const float4*)(ep + t * KEXP);
        float4 e1 = *(const float4*)(ep + t * KEXP + 4);
        float4 s0 = *(const float4*)(sp + t * KEXP);
        float4 s1 = *(const float4*)(sp + t * KEXP + 4);
        float ev[KEXP] = {e0.x, e0.y, e0.z, e0.w, e1.x, e1.y, e1.z, e1.w};
        float sv[KEXP] = {s0.x, s0.y, s0.z, s0.w, s1.x, s1.y, s1.z, s1.w};
        float y0 = 0.0f, y1 = 0.0f;
        #pragma unroll
        for (int k = 0; k < KEXP; k += 2) {
            m[k]     = fmaf(o[k],     m[k],     ev[k]     * iv);
            m[k + 1] = fmaf(o[k + 1], m[k + 1], ev[k + 1] * iv);
            y0 = fmaf(sv[k],     m[k],     y0);
            y1 = fmaf(sv[k + 1], m[k + 1], y1);
        }
        yp[(size_t)t * DIM] = y0 + y1;
    }
}

// ---------------------------------------------------------------------------
// LayerNorm in place on g_y: one warp per row
// ---------------------------------------------------------------------------
__global__ __launch_bounds__(256) void ln_kernel(const float* __restrict__ gamma,
                                                 const float* __restrict__ beta) {
    const int row  = blockIdx.x * 8 + (threadIdx.x >> 5);
    const int lane = threadIdx.x & 31;
    float4* yr = (float4*)(g_y + (size_t)row * DIM);

    float4 v[4];
    float sum = 0.0f, sq = 0.0f;
    #pragma unroll
    for (int j = 0; j < 4; j++) {
        v[j] = yr[lane + j * 32];
        sum += v[j].x + v[j].y + v[j].z + v[j].w;
        sq  = fmaf(v[j].x, v[j].x, sq);
        sq  = fmaf(v[j].y, v[j].y, sq);
        sq  = fmaf(v[j].z, v[j].z, sq);
        sq  = fmaf(v[j].w, v[j].w, sq);
    }
    #pragma unroll
    for (int off = 16; off > 0; off >>= 1) {
        sum += __shfl_xor_sync(0xFFFFFFFFu, sum, off);
        sq  += __shfl_xor_sync(0xFFFFFFFFu, sq, off);
    }
    float mu   = sum * (1.0f / DIM);
    float var  = sq * (1.0f / DIM) - mu * mu;
    float rstd = rsqrtf(var + LN_EPS);

    const float4* g4 = (const float4*)gamma;
    const float4* b4 = (const float4*)beta;
    #pragma unroll
    for (int j = 0; j < 4; j++) {
        int idx = lane + j * 32;
        float4 g = g4[idx], bb = b4[idx];
        float4 r;
        r.x = fmaf((v[j].x - mu) * rstd, g.x, bb.x);
        r.y = fmaf((v[j].y - mu) * rstd, g.y, bb.y);
        r.z = fmaf((v[j].z - mu) * rstd, g.z, bb.z);
        r.w = fmaf((v[j].w - mu) * rstd, g.w, bb.w);
        yr[idx] = r;
    }
}

// ---------------------------------------------------------------------------
// Launch
// ---------------------------------------------------------------------------
extern "C" void kernel_launch(void* const* d_in, const int* in_sizes, int n_in,
                              void* d_out, int out_size) {
    const float* x       = (const float*)d_in[0];
    const float* W_i     = (const float*)d_in[1];
    const float* W_e     = (const float*)d_in[2];
    const float* W_s     = (const float*)d_in[3];
    const float* o_param = (const float*)d_in[4];
    const float* gamma   = (const float*)d_in[5];
    const float* beta    = (const float*)d_in[6];
    const float* W_out   = (const float*)d_in[7];
    float* out = (float*)d_out;

    dim3 gemm_grid(DIM / 128, ROWS / 128);   // (4, 128)

    sgemm1_kernel<<<gemm_grid, 256>>>(x, W_i);
    es_kernel<<<ROWS / 8, 256>>>(x, W_e, W_s);
    scan_local_kernel<<<dim3(NCHUNK, BATCH), DIM>>>(o_param);
    scan_prefix_kernel<<<BATCH, DIM>>>(o_param);
    scan_apply_kernel<<<dim3(NCHUNK, BATCH), DIM>>>(o_param);
    ln_kernel<<<ROWS / 8, 256>>>(gamma, beta);
    sgemm2_kernel<<<gemm_grid, 256>>>(W_out, out);
}

// round 3
// speedup vs baseline: 1.7045x; 1.7045x over previous
#include <cuda_runtime.h>
#include <cuda_bf16.h>
#include <math.h>
#include <cstdint>

// Problem constants
#define BATCH 4
#define SEQ   4096
#define DIM   512
#define KEXP  8
#define ROWS  (BATCH*SEQ)        // 16384 token rows
#define CHUNK 128                // scan chunk length
#define NCHUNK (SEQ/CHUNK)       // 32 chunks
#define INV_TAU (1.0f/16.0f)
#define LN_EPS 1e-5f

// ---------------------------------------------------------------------------
// Scratch (static device globals)
// ---------------------------------------------------------------------------
__device__ float g_i[ROWS * DIM];                       // x @ W_i (fp32)
__device__ float g_e[ROWS * KEXP];
__device__ float g_s[ROWS * KEXP];
__device__ float g_S[BATCH * NCHUNK * KEXP * DIM];
__device__ float g_P[BATCH * NCHUNK * KEXP * DIM];
__device__ float g_y[ROWS * DIM];                       // scan output (fp32)
__device__ __nv_bfloat16 g_xhi[ROWS * DIM];
__device__ __nv_bfloat16 g_xlo[ROWS * DIM];
__device__ __nv_bfloat16 g_yhi[ROWS * DIM];
__device__ __nv_bfloat16 g_ylo[ROWS * DIM];
__device__ __nv_bfloat16 g_wihi[DIM * DIM];             // W_i^T  [N,K] bf16 hi
__device__ __nv_bfloat16 g_wilo[DIM * DIM];
__device__ __nv_bfloat16 g_wohi[DIM * DIM];             // W_out^T
__device__ __nv_bfloat16 g_wolo[DIM * DIM];

__device__ __forceinline__ void split_bf16(float v, __nv_bfloat16& h, __nv_bfloat16& l) {
    h = __float2bfloat16(v);
    l = __float2bfloat16(v - __bfloat162float(h));
}

// ---------------------------------------------------------------------------
// PTX primitives (all baseline sm_80+ — legal for compute_103 PTX target)
// ---------------------------------------------------------------------------
__device__ __forceinline__ uint32_t smem_to_u32(const void* p) {
    uint32_t a;
    asm("{ .reg .u64 t; cvta.to.shared.u64 t, %1; cvt.u32.u64 %0, t; }" : "=r"(a) : "l"(p));
    return a;
}

__device__ __forceinline__ void cp16(uint32_t dst, const void* src) {
    asm volatile("cp.async.cg.shared.global [%0], [%1], 16;" :: "r"(dst), "l"(src));
}
__device__ __forceinline__ void cp_commit() {
    asm volatile("cp.async.commit_group;" ::: "memory");
}
template <int N>
__device__ __forceinline__ void cp_wait() {
    asm volatile("cp.async.wait_group %0;" :: "n"(N) : "memory");
}

__device__ __forceinline__ void ldsm4(uint32_t* r, uint32_t addr) {
    asm volatile("ldmatrix.sync.aligned.m8n8.x4.shared.b16 {%0,%1,%2,%3}, [%4];"
                 : "=r"(r[0]), "=r"(r[1]), "=r"(r[2]), "=r"(r[3]) : "r"(addr));
}

__device__ __forceinline__ void mma16816(float* c, const uint32_t* a, const uint32_t* b) {
    asm volatile(
        "mma.sync.aligned.m16n8k16.row.col.f32.bf16.bf16.f32 "
        "{%0,%1,%2,%3}, {%4,%5,%6,%7}, {%8,%9}, {%0,%1,%2,%3};"
        : "+f"(c[0]), "+f"(c[1]), "+f"(c[2]), "+f"(c[3])
        : "r"(a[0]), "r"(a[1]), "r"(a[2]), "r"(a[3]), "r"(b[0]), "r"(b[1]));
}

// Swizzle for 32B rows packed into 128B groups: XOR bits[4:5] with bits[7:8]
__device__ __forceinline__ uint32_t sw32(uint32_t off) {
    return off ^ (((off >> 7) & 3u) << 4);
}

// ---------------------------------------------------------------------------
// HMMA split-precision GEMM: C[Mx512] = A * B^T
// A: hi/lo bf16 [M,512] row-major; B: hi/lo bf16 [512,512] = W^T, [N,K] row-major
// CTA tile 128(M)x128(N), BK=16, 8 warps of 32x64, double-buffered cp.async.
// SMEM: 2 buffers x 4 tiles (Ahi,Alo,Bhi,Blo) x 128 rows x 32B = 32 KB static.
// ---------------------------------------------------------------------------
#define NKI (DIM/16)             // 32 k-iterations
#define TILE_B 4096              // bytes per tile (128 rows x 32B)

struct GemmSmem { char buf[2][4][TILE_B]; };

__device__ __forceinline__ void gemm_load(uint32_t sbase, int buf, int c,
                                          const __nv_bfloat16* Ahi, const __nv_bfloat16* Alo,
                                          const __nv_bfloat16* Bhi, const __nv_bfloat16* Blo,
                                          int row0, int col0, int tid) {
    const int r = tid >> 1;              // 0..127
    const int h = tid & 1;               // 16B half of the 32B row
    const uint32_t soff = sw32((uint32_t)(r * 32 + h * 16));
    const size_t ga = (size_t)(row0 + r) * DIM + c * 16 + h * 8;
    const size_t gb = (size_t)(col0 + r) * DIM + c * 16 + h * 8;
    const uint32_t base = sbase + (uint32_t)(buf * 4 * TILE_B);
    cp16(base + 0 * TILE_B + soff, Ahi + ga);
    cp16(base + 1 * TILE_B + soff, Alo + ga);
    cp16(base + 2 * TILE_B + soff, Bhi + gb);
    cp16(base + 3 * TILE_B + soff, Blo + gb);
}

__device__ __forceinline__ void gemm_body(const __nv_bfloat16* __restrict__ Ahi,
                                          const __nv_bfloat16* __restrict__ Alo,
                                          const __nv_bfloat16* __restrict__ Bhi,
                                          const __nv_bfloat16* __restrict__ Blo,
                                          float* __restrict__ C) {
    __shared__ GemmSmem sm;
    const uint32_t sbase = smem_to_u32(&sm);
    const int tid = threadIdx.x;
    const int lane = tid & 31;
    const int wid = tid >> 5;
    const int warp_m = wid >> 1;         // 0..3 -> 32-row slice
    const int warp_n = wid & 1;          // 0..1 -> 64-col slice
    const int row0 = blockIdx.y * 128;
    const int col0 = blockIdx.x * 128;

    // ldmatrix lane addressing: row = lane&15, 16B column half = lane>>4
    const int lr = lane & 15;
    const int lc = (lane >> 4) & 1;

    float acc[2][8][4];
    #pragma unroll
    for (int m = 0; m < 2; m++)
        #pragma unroll
        for (int n = 0; n < 8; n++)
            #pragma unroll
            for (int q = 0; q < 4; q++) acc[m][n][q] = 0.0f;

    gemm_load(sbase, 0, 0, Ahi, Alo, Bhi, Blo, row0, col0, tid);
    cp_commit();

    for (int c = 0; c < NKI; ++c) {
        const int buf = c & 1;
        if (c + 1 < NKI) {
            gemm_load(sbase, buf ^ 1, c + 1, Ahi, Alo, Bhi, Blo, row0, col0, tid);
            cp_commit();
            cp_wait<1>();
        } else {
            cp_wait<0>();
        }
        __syncthreads();

        const uint32_t bb = sbase + (uint32_t)(buf * 4 * TILE_B);
        // ldmatrix source addresses (swizzled)
        uint32_t aAddr[2], bAddr[4];
        #pragma unroll
        for (int m = 0; m < 2; m++) {
            const int row = warp_m * 32 + m * 16 + lr;
            aAddr[m] = sw32((uint32_t)(row * 32 + lc * 16));
        }
        #pragma unroll
        for (int q = 0; q < 4; q++) {
            const int row = warp_n * 64 + q * 16 + lr;
            bAddr[q] = sw32((uint32_t)(row * 32 + lc * 16));
        }

        uint32_t a[2][4], b[8][2];

        // combo 1: Ahi x Bhi
        ldsm4(a[0], bb + 0 * TILE_B + aAddr[0]);
        ldsm4(a[1], bb + 0 * TILE_B + aAddr[1]);
        #pragma unroll
        for (int q = 0; q < 4; q++) {
            uint32_t t4[4];
            ldsm4(t4, bb + 2 * TILE_B + bAddr[q]);
            b[2*q][0] = t4[0]; b[2*q+1][0] = t4[1];
            b[2*q][1] = t4[2]; b[2*q+1][1] = t4[3];
        }
        #pragma unroll
        for (int m = 0; m < 2; m++)
            #pragma unroll
            for (int n = 0; n < 8; n++) mma16816(acc[m][n], a[m], b[n]);

        // combo 2: Alo x Bhi (reuse B)
        ldsm4(a[0], bb + 1 * TILE_B + aAddr[0]);
        ldsm4(a[1], bb + 1 * TILE_B + aAddr[1]);
        #pragma unroll
        for (int m = 0; m < 2; m++)
            #pragma unroll
            for (int n = 0; n < 8; n++) mma16816(acc[m][n], a[m], b[n]);

        // combo 3: Ahi x Blo
        ldsm4(a[0], bb + 0 * TILE_B + aAddr[0]);
        ldsm4(a[1], bb + 0 * TILE_B + aAddr[1]);
        #pragma unroll
        for (int q = 0; q < 4; q++) {
            uint32_t t4[4];
            ldsm4(t4, bb + 3 * TILE_B + bAddr[q]);
            b[2*q][0] = t4[0]; b[2*q+1][0] = t4[1];
            b[2*q][1] = t4[2]; b[2*q+1][1] = t4[3];
        }
        #pragma unroll
        for (int m = 0; m < 2; m++)
            #pragma unroll
            for (int n = 0; n < 8; n++) mma16816(acc[m][n], a[m], b[n]);

        __syncthreads();
    }

    // Epilogue: fragment layout -> C
    const int tr = lane >> 2;            // 0..7
    const int tc = (lane & 3) * 2;
    #pragma unroll
    for (int m = 0; m < 2; m++) {
        const int rbase = row0 + warp_m * 32 + m * 16 + tr;
        #pragma unroll
        for (int n = 0; n < 8; n++) {
            const int col = col0 + warp_n * 64 + n * 8 + tc;
            float* p0 = C + (size_t)rbase * DIM + col;
            float* p1 = C + (size_t)(rbase + 8) * DIM + col;
            *(float2*)p0 = make_float2(acc[m][n][0], acc[m][n][1]);
            *(float2*)p1 = make_float2(acc[m][n][2], acc[m][n][3]);
        }
    }
}

__global__ __launch_bounds__(256, 2) void gemm1_kernel() {
    gemm_body(g_xhi, g_xlo, g_wihi, g_wilo, g_i);
}
__global__ __launch_bounds__(256, 2) void gemm2_kernel(float* __restrict__ out) {
    gemm_body(g_yhi, g_ylo, g_wohi, g_wolo, out);
}

// ---------------------------------------------------------------------------
// Convert x (fp32) -> hi/lo bf16
// ---------------------------------------------------------------------------
__global__ __launch_bounds__(256) void convert_x_kernel(const float* __restrict__ x) {
    const size_t i = (size_t)blockIdx.x * 256 + threadIdx.x;   // float4 index
    float4 v = ((const float4*)x)[i];
    __nv_bfloat16 h[4], l[4];
    split_bf16(v.x, h[0], l[0]);
    split_bf16(v.y, h[1], l[1]);
    split_bf16(v.z, h[2], l[2]);
    split_bf16(v.w, h[3], l[3]);
    ((uint2*)g_xhi)[i] = *(uint2*)h;
    ((uint2*)g_xlo)[i] = *(uint2*)l;
}

// ---------------------------------------------------------------------------
// Transpose + split weights: W [K,N] fp32 -> W^T [N,K] bf16 hi/lo
// ---------------------------------------------------------------------------
__global__ __launch_bounds__(256) void convert_wt_kernel(const float* __restrict__ W_i,
                                                         const float* __restrict__ W_out) {
    __shared__ float t[32][33];
    const int z = blockIdx.z;
    const float* W = z ? W_out : W_i;
    __nv_bfloat16* Dhi = z ? g_wohi : g_wihi;
    __nv_bfloat16* Dlo = z ? g_wolo : g_wilo;
    const int n0 = blockIdx.x * 32, k0 = blockIdx.y * 32;
    const int tx = threadIdx.x, ty = threadIdx.y;
    #pragma unroll
    for (int j = 0; j < 4; ++j)
        t[ty + j * 8][tx] = W[(size_t)(k0 + ty + j * 8) * DIM + n0 + tx];
    __syncthreads();
    #pragma unroll
    for (int j = 0; j < 4; ++j) {
        const int nn = ty + j * 8;
        const float v = t[tx][nn];                  // element (k0+tx, n0+nn)
        __nv_bfloat16 h, l;
        split_bf16(v, h, l);
        Dhi[(size_t)(n0 + nn) * DIM + k0 + tx] = h;
        Dlo[(size_t)(n0 + nn) * DIM + k0 + tx] = l;
    }
}

// ---------------------------------------------------------------------------
// e = x @ W_e, s = x @ W_s (one warp per token row)
// ---------------------------------------------------------------------------
__global__ __launch_bounds__(256) void es_kernel(const float* __restrict__ x,
                                                 const float* __restrict__ W_e,
                                                 const float* __restrict__ W_s) {
    const int row  = blockIdx.x * 8 + (threadIdx.x >> 5);
    const int lane = threadIdx.x & 31;
    const float* xr = x + (size_t)row * DIM;

    float acc[16];
    #pragma unroll
    for (int k = 0; k < 16; k++) acc[k] = 0.0f;

    for (int d = lane; d < DIM; d += 32) {
        float xv = xr[d];
        float4 w0 = *(const float4*)(W_e + d * KEXP);
        float4 w1 = *(const float4*)(W_e + d * KEXP + 4);
        float4 v0 = *(const float4*)(W_s + d * KEXP);
        float4 v1 = *(const float4*)(W_s + d * KEXP + 4);
        acc[0]  = fmaf(xv, w0.x, acc[0]);  acc[1]  = fmaf(xv, w0.y, acc[1]);
        acc[2]  = fmaf(xv, w0.z, acc[2]);  acc[3]  = fmaf(xv, w0.w, acc[3]);
        acc[4]  = fmaf(xv, w1.x, acc[4]);  acc[5]  = fmaf(xv, w1.y, acc[5]);
        acc[6]  = fmaf(xv, w1.z, acc[6]);  acc[7]  = fmaf(xv, w1.w, acc[7]);
        acc[8]  = fmaf(xv, v0.x, acc[8]);  acc[9]  = fmaf(xv, v0.y, acc[9]);
        acc[10] = fmaf(xv, v0.z, acc[10]); acc[11] = fmaf(xv, v0.w, acc[11]);
        acc[12] = fmaf(xv, v1.x, acc[12]); acc[13] = fmaf(xv, v1.y, acc[13]);
        acc[14] = fmaf(xv, v1.z, acc[14]); acc[15] = fmaf(xv, v1.w, acc[15]);
    }
    #pragma unroll
    for (int off = 16; off > 0; off >>= 1) {
        #pragma unroll
        for (int k = 0; k < 16; k++)
            acc[k] += __shfl_xor_sync(0xFFFFFFFFu, acc[k], off);
    }
    if (lane == 0) {
        #pragma unroll
        for (int k = 0; k < 8; k++) g_e[(size_t)row * KEXP + k] = acc[k];
        #pragma unroll
        for (int k = 0; k < 8; k++) g_s[(size_t)row * KEXP + k] = acc[8 + k];
    }
}

// ---------------------------------------------------------------------------
// Decay helper
// ---------------------------------------------------------------------------
__device__ __forceinline__ void load_decay(const float* __restrict__ o_param,
                                           int d, float scale, float o[KEXP]) {
    #pragma unroll
    for (int k = 0; k < KEXP; k++) {
        float op = o_param[k * DIM + d];
        float ls = fminf(op, 0.0f) - log1pf(expf(-fabsf(op)));
        o[k] = expf(ls * scale);
    }
}

// ---------------------------------------------------------------------------
// Scan phase 1: per-chunk local end state
// ---------------------------------------------------------------------------
__global__ __launch_bounds__(DIM) void scan_local_kernel(const float* __restrict__ o_param) {
    const int c = blockIdx.x, b = blockIdx.y, d = threadIdx.x;
    float o[KEXP], m[KEXP];
    load_decay(o_param, d, INV_TAU, o);
    #pragma unroll
    for (int k = 0; k < KEXP; k++) m[k] = 0.0f;

    const int t0 = c * CHUNK;
    const float* ip = g_i + ((size_t)b * SEQ + t0) * DIM + d;
    const float* ep = g_e + ((size_t)b * SEQ + t0) * KEXP;

    #pragma unroll 2
    for (int t = 0; t < CHUNK; t++) {
        float iv = ip[(size_t)t * DIM];
        float4 e0 = *(const float4*)(ep + t * KEXP);
        float4 e1 = *(const float4*)(ep + t * KEXP + 4);
        float ev[KEXP] = {e0.x, e0.y, e0.z, e0.w, e1.x, e1.y, e1.z, e1.w};
        #pragma unroll
        for (int k = 0; k < KEXP; k++)
            m[k] = fmaf(o[k], m[k], ev[k] * iv);
    }
    #pragma unroll
    for (int k = 0; k < KEXP; k++)
        g_S[(((size_t)b * NCHUNK + c) * KEXP + k) * DIM + d] = m[k];
}

// ---------------------------------------------------------------------------
// Scan phase 2: prefix over chunks; grid (BATCH, 4); loads hoisted for MLP.
// ---------------------------------------------------------------------------
__global__ __launch_bounds__(DIM) void scan_prefix_kernel(const float* __restrict__ o_param) {
    const int b = blockIdx.x;
    const int kp = blockIdx.y * 2;
    const int d = threadIdx.x;

    float oL0, oL1;
    {
        float op0 = o_param[kp * DIM + d];
        float op1 = o_param[(kp + 1) * DIM + d];
        float ls0 = fminf(op0, 0.0f) - log1pf(expf(-fabsf(op0)));
        float ls1 = fminf(op1, 0.0f) - log1pf(expf(-fabsf(op1)));
        oL0 = expf(ls0 * (INV_TAU * (float)CHUNK));
        oL1 = expf(ls1 * (INV_TAU * (float)CHUNK));
    }

    float s0[NCHUNK], s1[NCHUNK];
    #pragma unroll
    for (int c = 0; c < NCHUNK; c++) {
        s0[c] = g_S[(((size_t)b * NCHUNK + c) * KEXP + kp) * DIM + d];
        s1[c] = g_S[(((size_t)b * NCHUNK + c) * KEXP + kp + 1) * DIM + d];
    }
    float p0 = 0.0f, p1 = 0.0f;
    #pragma unroll
    for (int c = 0; c < NCHUNK; c++) {
        g_P[(((size_t)b * NCHUNK + c) * KEXP + kp) * DIM + d] = p0;
        g_P[(((size_t)b * NCHUNK + c) * KEXP + kp + 1) * DIM + d] = p1;
        p0 = fmaf(oL0, p0, s0[c]);
        p1 = fmaf(oL1, p1, s1[c]);
    }
}

// ---------------------------------------------------------------------------
// Scan phase 3: replay chunk from prefix, emit y
// ---------------------------------------------------------------------------
__global__ __launch_bounds__(DIM) void scan_apply_kernel(const float* __restrict__ o_param) {
    const int c = blockIdx.x, b = blockIdx.y, d = threadIdx.x;
    float o[KEXP], m[KEXP];
    load_decay(o_param, d, INV_TAU, o);
    #pragma unroll
    for (int k = 0; k < KEXP; k++)
        m[k] = g_P[(((size_t)b * NCHUNK + c) * KEXP + k) * DIM + d];

    const int t0 = c * CHUNK;
    const float* ip = g_i + ((size_t)b * SEQ + t0) * DIM + d;
    const float* ep = g_e + ((size_t)b * SEQ + t0) * KEXP;
    const float* sp = g_s + ((size_t)b * SEQ + t0) * KEXP;
    float* yp = g_y + ((size_t)b * SEQ + t0) * DIM + d;

    #pragma unroll 2
    for (int t = 0; t < CHUNK; t++) {
        float iv = ip[(size_t)t * DIM];
        float4 e0 = *(const float4*)(ep + t * KEXP);
        float4 e1 = *(const float4*)(ep + t * KEXP + 4);
        float4 s0 = *(const float4*)(sp + t * KEXP);
        float4 s1 = *(const float4*)(sp + t * KEXP + 4);
        float ev[KEXP] = {e0.x, e0.y, e0.z, e0.w, e1.x, e1.y, e1.z, e1.w};
        float sv[KEXP] = {s0.x, s0.y, s0.z, s0.w, s1.x, s1.y, s1.z, s1.w};
        float y0 = 0.0f, y1 = 0.0f;
        #pragma unroll
        for (int k = 0; k < KEXP; k += 2) {
            m[k]     = fmaf(o[k],     m[k],     ev[k]     * iv);
            m[k + 1] = fmaf(o[k + 1], m[k + 1], ev[k + 1] * iv);
            y0 = fmaf(sv[k],     m[k],     y0);
            y1 = fmaf(sv[k + 1], m[k + 1], y1);
        }
        yp[(size_t)t * DIM] = y0 + y1;
    }
}

// ---------------------------------------------------------------------------
// LayerNorm on g_y -> hi/lo bf16 (inputs to GEMM2)
// ---------------------------------------------------------------------------
__global__ __launch_bounds__(256) void ln_kernel(const float* __restrict__ gamma,
                                                 const float* __restrict__ beta) {
    const int row  = blockIdx.x * 8 + (threadIdx.x >> 5);
    const int lane = threadIdx.x & 31;
    const float4* yr = (const float4*)(g_y + (size_t)row * DIM);

    float4 v[4];
    float sum = 0.0f, sq = 0.0f;
    #pragma unroll
    for (int j = 0; j < 4; j++) {
        v[j] = yr[lane + j * 32];
        sum += v[j].x + v[j].y + v[j].z + v[j].w;
        sq  = fmaf(v[j].x, v[j].x, sq);
        sq  = fmaf(v[j].y, v[j].y, sq);
        sq  = fmaf(v[j].z, v[j].z, sq);
        sq  = fmaf(v[j].w, v[j].w, sq);
    }
    #pragma unroll
    for (int off = 16; off > 0; off >>= 1) {
        sum += __shfl_xor_sync(0xFFFFFFFFu, sum, off);
        sq  += __shfl_xor_sync(0xFFFFFFFFu, sq, off);
    }
    const float mu   = sum * (1.0f / DIM);
    const float var  = sq * (1.0f / DIM) - mu * mu;
    const float rstd = rsqrtf(var + LN_EPS);

    const float4* g4 = (const float4*)gamma;
    const float4* b4 = (const float4*)beta;
    #pragma unroll
    for (int j = 0; j < 4; j++) {
        const int idx = lane + j * 32;
        float4 g = g4[idx], bb = b4[idx];
        float r[4];
        r[0] = fmaf((v[j].x - mu) * rstd, g.x, bb.x);
        r[1] = fmaf((v[j].y - mu) * rstd, g.y, bb.y);
        r[2] = fmaf((v[j].z - mu) * rstd, g.z, bb.z);
        r[3] = fmaf((v[j].w - mu) * rstd, g.w, bb.w);
        __nv_bfloat16 h[4], l[4];
        #pragma unroll
        for (int q = 0; q < 4; q++) split_bf16(r[q], h[q], l[q]);
        ((uint2*)(g_yhi + (size_t)row * DIM))[idx] = *(uint2*)h;
        ((uint2*)(g_ylo + (size_t)row * DIM))[idx] = *(uint2*)l;
    }
}

// ---------------------------------------------------------------------------
// Launch
// ---------------------------------------------------------------------------
extern "C" void kernel_launch(void* const* d_in, const int* in_sizes, int n_in,
                              void* d_out, int out_size) {
    const float* x       = (const float*)d_in[0];
    const float* W_i     = (const float*)d_in[1];
    const float* W_e     = (const float*)d_in[2];
    const float* W_s     = (const float*)d_in[3];
    const float* o_param = (const float*)d_in[4];
    const float* gamma   = (const float*)d_in[5];
    const float* beta    = (const float*)d_in[6];
    const float* W_out   = (const float*)d_in[7];
    float* out = (float*)d_out;

    convert_x_kernel<<<ROWS * DIM / 4 / 256, 256>>>(x);
    convert_wt_kernel<<<dim3(16, 16, 2), dim3(32, 8)>>>(W_i, W_out);
    gemm1_kernel<<<dim3(4, 128), 256>>>();
    es_kernel<<<ROWS / 8, 256>>>(x, W_e, W_s);
    scan_local_kernel<<<dim3(NCHUNK, BATCH), DIM>>>(o_param);
    scan_prefix_kernel<<<dim3(BATCH, KEXP / 2), DIM>>>(o_param);
    scan_apply_kernel<<<dim3(NCHUNK, BATCH), DIM>>>(o_param);
    ln_kernel<<<ROWS / 8, 256>>>(gamma, beta);
    gemm2_kernel<<<dim3(4, 128), 256>>>(out);
}

// round 5
// speedup vs baseline: 2.3491x; 1.3782x over previous
#include <cuda_runtime.h>
#include <cuda_fp16.h>
#include <math.h>
#include <cstdint>

// Problem constants
#define BATCH 4
#define SEQ   4096
#define DIM   512
#define KEXP  8
#define ROWS  (BATCH*SEQ)        // 16384 token rows
#define CHUNK 128                // scan chunk length
#define NCHUNK (SEQ/CHUNK)       // 32 chunks
#define INV_TAU (1.0f/16.0f)
#define LN_EPS 1e-5f

// ---------------------------------------------------------------------------
// Scratch (static device globals)
// ---------------------------------------------------------------------------
__device__ float g_i[ROWS * DIM];                       // x @ W_i (fp32)
__device__ float g_e[ROWS * KEXP];
__device__ float g_s[ROWS * KEXP];
__device__ float g_S[BATCH * NCHUNK * KEXP * DIM];
__device__ float g_P[BATCH * NCHUNK * KEXP * DIM];
__device__ __half g_xhi[ROWS * DIM];
__device__ __half g_xlo[ROWS * DIM];
__device__ __half g_yhi[ROWS * DIM];
__device__ __half g_ylo[ROWS * DIM];
__device__ __half g_wi[DIM * DIM];                      // W_i^T  [N,K] fp16
__device__ __half g_wo[DIM * DIM];                      // W_out^T [N,K] fp16
__device__ __half g_wes[16 * DIM];                      // [W_e|W_s]^T [16,K] fp16

__device__ __forceinline__ void split_half(float v, __half& h, __half& l) {
    h = __float2half(v);
    l = __float2half(v - __half2float(h));
}

// ---------------------------------------------------------------------------
// PTX primitives (baseline sm_80+ — legal for compute_103 PTX target)
// ---------------------------------------------------------------------------
__device__ __forceinline__ uint32_t smem_to_u32(const void* p) {
    uint32_t a;
    asm("{ .reg .u64 t; cvta.to.shared.u64 t, %1; cvt.u32.u64 %0, t; }" : "=r"(a) : "l"(p));
    return a;
}

__device__ __forceinline__ void cp16(uint32_t dst, const void* src) {
    asm volatile("cp.async.cg.shared.global [%0], [%1], 16;" :: "r"(dst), "l"(src));
}
__device__ __forceinline__ void cp_commit() {
    asm volatile("cp.async.commit_group;" ::: "memory");
}
template <int N>
__device__ __forceinline__ void cp_wait() {
    asm volatile("cp.async.wait_group %0;" :: "n"(N) : "memory");
}

__device__ __forceinline__ void ldsm4(uint32_t* r, uint32_t addr) {
    asm volatile("ldmatrix.sync.aligned.m8n8.x4.shared.b16 {%0,%1,%2,%3}, [%4];"
                 : "=r"(r[0]), "=r"(r[1]), "=r"(r[2]), "=r"(r[3]) : "r"(addr));
}

__device__ __forceinline__ void mma16816(float* c, const uint32_t* a, const uint32_t* b) {
    asm volatile(
        "mma.sync.aligned.m16n8k16.row.col.f32.f16.f16.f32 "
        "{%0,%1,%2,%3}, {%4,%5,%6,%7}, {%8,%9}, {%0,%1,%2,%3};"
        : "+f"(c[0]), "+f"(c[1]), "+f"(c[2]), "+f"(c[3])
        : "r"(a[0]), "r"(a[1]), "r"(a[2]), "r"(a[3]), "r"(b[0]), "r"(b[1]));
}

// Swizzle for 32B rows packed into 128B groups: XOR bits[4:5] with bits[7:8]
__device__ __forceinline__ uint32_t sw32(uint32_t off) {
    return off ^ (((off >> 7) & 3u) << 4);
}

// ---------------------------------------------------------------------------
// HMMA 2-term fp16 GEMM: C[Mx512] = (Ahi+Alo) * B^T
// A: hi/lo fp16 [M,512] row-major; B: fp16 [512,512] = W^T, [N,K] row-major
// CTA tile 128(M)x128(N), BK=16, 8 warps of 32x64, double-buffered cp.async.
// ---------------------------------------------------------------------------
#define NKI (DIM/16)             // 32 k-iterations
#define TILE_B 4096              // bytes per tile (128 rows x 32B)

struct __align__(128) GemmSmem { char buf[2][3][TILE_B]; };   // Ahi, Alo, B

__device__ __forceinline__ void gemm_load(uint32_t sbase, int buf, int c,
                                          const __half* Ahi, const __half* Alo,
                                          const __half* B,
                                          int row0, int col0, int tid) {
    const int r = tid >> 1;              // 0..127
    const int h = tid & 1;               // 16B half of the 32B row
    const uint32_t soff = sw32((uint32_t)(r * 32 + h * 16));
    const size_t ga = (size_t)(row0 + r) * DIM + c * 16 + h * 8;
    const size_t gb = (size_t)(col0 + r) * DIM + c * 16 + h * 8;
    const uint32_t base = sbase + (uint32_t)(buf * 3 * TILE_B);
    cp16(base + 0 * TILE_B + soff, Ahi + ga);
    cp16(base + 1 * TILE_B + soff, Alo + ga);
    cp16(base + 2 * TILE_B + soff, B + gb);
}

__device__ __forceinline__ void gemm_body(const __half* __restrict__ Ahi,
                                          const __half* __restrict__ Alo,
                                          const __half* __restrict__ B,
                                          float* __restrict__ C) {
    __shared__ GemmSmem sm;
    const uint32_t sbase = smem_to_u32(&sm);
    const int tid = threadIdx.x;
    const int lane = tid & 31;
    const int wid = tid >> 5;
    const int warp_m = wid >> 1;         // 0..3 -> 32-row slice
    const int warp_n = wid & 1;          // 0..1 -> 64-col slice
    const int row0 = blockIdx.y * 128;
    const int col0 = blockIdx.x * 128;

    const int lr = lane & 15;
    const int lc = (lane >> 4) & 1;

    float acc[2][8][4];
    #pragma unroll
    for (int m = 0; m < 2; m++)
        #pragma unroll
        for (int n = 0; n < 8; n++)
            #pragma unroll
            for (int q = 0; q < 4; q++) acc[m][n][q] = 0.0f;

    gemm_load(sbase, 0, 0, Ahi, Alo, B, row0, col0, tid);
    cp_commit();

    // ldmatrix source addresses (swizzled), loop-invariant
    uint32_t aAddr[2], bAddr[4];
    #pragma unroll
    for (int m = 0; m < 2; m++)
        aAddr[m] = sw32((uint32_t)((warp_m * 32 + m * 16 + lr) * 32 + lc * 16));
    #pragma unroll
    for (int q = 0; q < 4; q++)
        bAddr[q] = sw32((uint32_t)((warp_n * 64 + q * 16 + lr) * 32 + lc * 16));

    for (int c = 0; c < NKI; ++c) {
        const int buf = c & 1;
        if (c + 1 < NKI) {
            gemm_load(sbase, buf ^ 1, c + 1, Ahi, Alo, B, row0, col0, tid);
            cp_commit();
            cp_wait<1>();
        } else {
            cp_wait<0>();
        }
        __syncthreads();

        const uint32_t bb = sbase + (uint32_t)(buf * 3 * TILE_B);
        uint32_t a[2][4], b[8][2];

        // B fragments (shared by both combos)
        #pragma unroll
        for (int q = 0; q < 4; q++) {
            uint32_t t4[4];
            ldsm4(t4, bb + 2 * TILE_B + bAddr[q]);
            b[2*q][0] = t4[0]; b[2*q+1][0] = t4[1];
            b[2*q][1] = t4[2]; b[2*q+1][1] = t4[3];
        }

        // combo 1: Ahi x B
        ldsm4(a[0], bb + 0 * TILE_B + aAddr[0]);
        ldsm4(a[1], bb + 0 * TILE_B + aAddr[1]);
        #pragma unroll
        for (int m = 0; m < 2; m++)
            #pragma unroll
            for (int n = 0; n < 8; n++) mma16816(acc[m][n], a[m], b[n]);

        // combo 2: Alo x B
        ldsm4(a[0], bb + 1 * TILE_B + aAddr[0]);
        ldsm4(a[1], bb + 1 * TILE_B + aAddr[1]);
        #pragma unroll
        for (int m = 0; m < 2; m++)
            #pragma unroll
            for (int n = 0; n < 8; n++) mma16816(acc[m][n], a[m], b[n]);

        __syncthreads();
    }

    // Epilogue
    const int tr = lane >> 2;
    const int tc = (lane & 3) * 2;
    #pragma unroll
    for (int m = 0; m < 2; m++) {
        const int rbase = row0 + warp_m * 32 + m * 16 + tr;
        #pragma unroll
        for (int n = 0; n < 8; n++) {
            const int col = col0 + warp_n * 64 + n * 8 + tc;
            float* p0 = C + (size_t)rbase * DIM + col;
            float* p1 = C + (size_t)(rbase + 8) * DIM + col;
            *(float2*)p0 = make_float2(acc[m][n][0], acc[m][n][1]);
            *(float2*)p1 = make_float2(acc[m][n][2], acc[m][n][3]);
        }
    }
}

__global__ __launch_bounds__(256, 2) void gemm1_kernel() {
    gemm_body(g_xhi, g_xlo, g_wi, g_i);
}
__global__ __launch_bounds__(256, 2) void gemm2_kernel(float* __restrict__ out) {
    gemm_body(g_yhi, g_ylo, g_wo, out);
}

// ---------------------------------------------------------------------------
// es via HMMA: [e|s][Mx16] = (xhi+xlo) * Wes^T.  Wes^T fp16 [16,512] in SMEM.
// CTA: 128 threads (4 warps), 128 rows. Warp: 32 rows (2 m-tiles) x 16 cols.
// ES_PITCH is in HALVES and must exceed 512 data columns: 520 halves
// (1040 B/row; +4-bank skew per row -> conflict-free B loads).
// ---------------------------------------------------------------------------
#define ES_PITCH 520

struct __align__(128) EsSmem {
    char abuf[2][2][TILE_B];     // [buf][hi/lo]
    __half w[16 * ES_PITCH];     // 16640 B
};

__global__ __launch_bounds__(128, 3) void es_mma_kernel() {
    __shared__ EsSmem sm;
    const uint32_t sbase = smem_to_u32(&sm);
    const uint32_t wbase = smem_to_u32(sm.w);
    const int tid = threadIdx.x;
    const int lane = tid & 31;
    const int wid = tid >> 5;            // 0..3
    const int row0 = blockIdx.x * 128;

    // Fill W smem: 16 rows x 512 halves, pitch ES_PITCH halves
    {
        const int row = tid >> 3;              // 0..15
        const int colb = (tid & 7) * 64;       // 0..448
        #pragma unroll
        for (int q = 0; q < 8; ++q) {
            uint4 v = *(const uint4*)(g_wes + row * DIM + colb + q * 8);
            *(uint4*)(sm.w + row * ES_PITCH + colb + q * 8) = v;
        }
    }

    // Preload A k-iter 0
    const int r = tid;                         // 128 rows, 1 per thread
    {
        #pragma unroll
        for (int j = 0; j < 4; ++j) {
            const int tile = j >> 1, h = j & 1;
            const __half* src = tile ? g_xlo : g_xhi;
            cp16(sbase + (uint32_t)(tile * TILE_B) + sw32((uint32_t)(r * 32 + h * 16)),
                 src + (size_t)(row0 + r) * DIM + h * 8);
        }
        cp_commit();
    }

    const int lr = lane & 15;
    const int lc = (lane >> 4) & 1;
    uint32_t aAddr[2];
    #pragma unroll
    for (int m = 0; m < 2; m++)
        aAddr[m] = sw32((uint32_t)((wid * 32 + m * 16 + lr) * 32 + lc * 16));

    float acc[2][2][4];
    #pragma unroll
    for (int m = 0; m < 2; m++)
        #pragma unroll
        for (int n = 0; n < 2; n++)
            #pragma unroll
            for (int q = 0; q < 4; q++) acc[m][n][q] = 0.0f;

    __syncthreads();   // W smem ready

    for (int c = 0; c < NKI; ++c) {
        const int buf = c & 1;
        if (c + 1 < NKI) {
            #pragma unroll
            for (int j = 0; j < 4; ++j) {
                const int tile = j >> 1, h = j & 1;
                const __half* src = tile ? g_xlo : g_xhi;
                cp16(sbase + (uint32_t)(((buf ^ 1) * 2 + tile) * TILE_B)
                           + sw32((uint32_t)(r * 32 + h * 16)),
                     src + (size_t)(row0 + r) * DIM + (c + 1) * 16 + h * 8);
            }
            cp_commit();
            cp_wait<1>();
        } else {
            cp_wait<0>();
        }
        __syncthreads();

        // B fragments from W smem (direct LDS.32, skewed pitch)
        uint32_t b[2][2];
        #pragma unroll
        for (int nt = 0; nt < 2; ++nt) {
            const uint32_t base = wbase
                + (uint32_t)(((nt * 8 + (lane >> 2)) * ES_PITCH + c * 16 + (lane & 3) * 2) * 2);
            asm volatile("ld.shared.b32 %0, [%1];" : "=r"(b[nt][0]) : "r"(base));
            asm volatile("ld.shared.b32 %0, [%1];" : "=r"(b[nt][1]) : "r"(base + 16));
        }

        const uint32_t ab = sbase + (uint32_t)(buf * 2 * TILE_B);
        uint32_t a[4];
        // combo 1: xhi
        #pragma unroll
        for (int m = 0; m < 2; m++) {
            ldsm4(a, ab + aAddr[m]);
            mma16816(acc[m][0], a, b[0]);
            mma16816(acc[m][1], a, b[1]);
        }
        // combo 2: xlo
        #pragma unroll
        for (int m = 0; m < 2; m++) {
            ldsm4(a, ab + TILE_B + aAddr[m]);
            mma16816(acc[m][0], a, b[0]);
            mma16816(acc[m][1], a, b[1]);
        }
        __syncthreads();
    }

    // Epilogue: nt0 -> e, nt1 -> s
    const int tr = lane >> 2;
    const int tc = (lane & 3) * 2;
    #pragma unroll
    for (int m = 0; m < 2; m++) {
        const int rbase = row0 + wid * 32 + m * 16 + tr;
        #pragma unroll
        for (int nt = 0; nt < 2; nt++) {
            float* dst = nt ? g_s : g_e;
            *(float2*)(dst + (size_t)rbase * KEXP + tc) =
                make_float2(acc[m][nt][0], acc[m][nt][1]);
            *(float2*)(dst + (size_t)(rbase + 8) * KEXP + tc) =
                make_float2(acc[m][nt][2], acc[m][nt][3]);
        }
    }
}

// ---------------------------------------------------------------------------
// Conversions
// ---------------------------------------------------------------------------
__global__ __launch_bounds__(256) void convert_x_kernel(const float* __restrict__ x) {
    const size_t i = (size_t)blockIdx.x * 256 + threadIdx.x;   // float4 index
    float4 v = ((const float4*)x)[i];
    __half h[4], l[4];
    split_half(v.x, h[0], l[0]);
    split_half(v.y, h[1], l[1]);
    split_half(v.z, h[2], l[2]);
    split_half(v.w, h[3], l[3]);
    ((uint2*)g_xhi)[i] = *(uint2*)h;
    ((uint2*)g_xlo)[i] = *(uint2*)l;
}

__global__ __launch_bounds__(256) void convert_w_kernel(const float* __restrict__ W_i,
                                                        const float* __restrict__ W_out) {
    __shared__ float t[32][33];
    const int z = blockIdx.z;
    const float* W = z ? W_out : W_i;
    __half* D = z ? g_wo : g_wi;
    const int n0 = blockIdx.x * 32, k0 = blockIdx.y * 32;
    const int tx = threadIdx.x, ty = threadIdx.y;
    #pragma unroll
    for (int j = 0; j < 4; ++j)
        t[ty + j * 8][tx] = W[(size_t)(k0 + ty + j * 8) * DIM + n0 + tx];
    __syncthreads();
    #pragma unroll
    for (int j = 0; j < 4; ++j) {
        const int nn = ty + j * 8;
        D[(size_t)(n0 + nn) * DIM + k0 + tx] = __float2half(t[tx][nn]);
    }
}

__global__ __launch_bounds__(256) void convert_wes_kernel(const float* __restrict__ W_e,
                                                          const float* __restrict__ W_s) {
    for (int e = threadIdx.x; e < 16 * DIM; e += 256) {
        const int j = e >> 9, d = e & 511;
        const float v = (j < 8) ? W_e[d * KEXP + j] : W_s[d * KEXP + j - 8];
        g_wes[e] = __float2half(v);
    }
}

// ---------------------------------------------------------------------------
// Decay helper
// ---------------------------------------------------------------------------
__device__ __forceinline__ void load_decay(const float* __restrict__ o_param,
                                           int d, float scale, float o[KEXP]) {
    #pragma unroll
    for (int k = 0; k < KEXP; k++) {
        float op = o_param[k * DIM + d];
        float ls = fminf(op, 0.0f) - log1pf(expf(-fabsf(op)));
        o[k] = expf(ls * scale);
    }
}

// ---------------------------------------------------------------------------
// Scan phase 1: per-chunk local end state
// ---------------------------------------------------------------------------
__global__ __launch_bounds__(DIM) void scan_local_kernel(const float* __restrict__ o_param) {
    const int c = blockIdx.x, b = blockIdx.y, d = threadIdx.x;
    float o[KEXP], m[KEXP];
    load_decay(o_param, d, INV_TAU, o);
    #pragma unroll
    for (int k = 0; k < KEXP; k++) m[k] = 0.0f;

    const int t0 = c * CHUNK;
    const float* ip = g_i + ((size_t)b * SEQ + t0) * DIM + d;
    const float* ep = g_e + ((size_t)b * SEQ + t0) * KEXP;

    #pragma unroll 2
    for (int t = 0; t < CHUNK; t++) {
        float iv = ip[(size_t)t * DIM];
        float4 e0 = *(const float4*)(ep + t * KEXP);
        float4 e1 = *(const float4*)(ep + t * KEXP + 4);
        float ev[KEXP] = {e0.x, e0.y, e0.z, e0.w, e1.x, e1.y, e1.z, e1.w};
        #pragma unroll
        for (int k = 0; k < KEXP; k++)
            m[k] = fmaf(o[k], m[k], ev[k] * iv);
    }
    #pragma unroll
    for (int k = 0; k < KEXP; k++)
        g_S[(((size_t)b * NCHUNK + c) * KEXP + k) * DIM + d] = m[k];
}

// ---------------------------------------------------------------------------
// Scan phase 2: prefix over chunks; loads hoisted for MLP.
// ---------------------------------------------------------------------------
__global__ __launch_bounds__(DIM) void scan_prefix_kernel(const float* __restrict__ o_param) {
    const int b = blockIdx.x;
    const int kp = blockIdx.y * 2;
    const int d = threadIdx.x;

    float oL0, oL1;
    {
        float op0 = o_param[kp * DIM + d];
        float op1 = o_param[(kp + 1) * DIM + d];
        float ls0 = fminf(op0, 0.0f) - log1pf(expf(-fabsf(op0)));
        float ls1 = fminf(op1, 0.0f) - log1pf(expf(-fabsf(op1)));
        oL0 = expf(ls0 * (INV_TAU * (float)CHUNK));
        oL1 = expf(ls1 * (INV_TAU * (float)CHUNK));
    }

    float s0[NCHUNK], s1[NCHUNK];
    #pragma unroll
    for (int c = 0; c < NCHUNK; c++) {
        s0[c] = g_S[(((size_t)b * NCHUNK + c) * KEXP + kp) * DIM + d];
        s1[c] = g_S[(((size_t)b * NCHUNK + c) * KEXP + kp + 1) * DIM + d];
    }
    float p0 = 0.0f, p1 = 0.0f;
    #pragma unroll
    for (int c = 0; c < NCHUNK; c++) {
        g_P[(((size_t)b * NCHUNK + c) * KEXP + kp) * DIM + d] = p0;
        g_P[(((size_t)b * NCHUNK + c) * KEXP + kp + 1) * DIM + d] = p1;
        p0 = fmaf(oL0, p0, s0[c]);
        p1 = fmaf(oL1, p1, s1[c]);
    }
}

// ---------------------------------------------------------------------------
// Scan phase 3 + LayerNorm fused: replay chunk, block-reduce LN over d=512,
// emit fp16 hi/lo directly (g_y round-trip eliminated).
// grid (NCHUNK, BATCH), block 512 (= DIM), 16 warps.
// ---------------------------------------------------------------------------
#define TG 16   // timesteps buffered per group

__global__ __launch_bounds__(DIM) void scan_apply_ln_kernel(const float* __restrict__ o_param,
                                                            const float* __restrict__ gamma,
                                                            const float* __restrict__ beta) {
    __shared__ float ybuf[TG][DIM];
    __shared__ float psum[TG][16];
    __shared__ float psq[TG][16];
    __shared__ float smu[TG], srstd[TG];

    const int c = blockIdx.x, b = blockIdx.y, d = threadIdx.x;
    const int lane = d & 31, warp = d >> 5;

    float o[KEXP], m[KEXP];
    load_decay(o_param, d, INV_TAU, o);
    #pragma unroll
    for (int k = 0; k < KEXP; k++)
        m[k] = g_P[(((size_t)b * NCHUNK + c) * KEXP + k) * DIM + d];

    const float gam = gamma[d];
    const float bet = beta[d];

    const int t0 = c * CHUNK;
    const size_t rowbase = (size_t)b * SEQ + t0;
    const float* ip = g_i + rowbase * DIM + d;
    const float* ep = g_e + rowbase * KEXP;
    const float* sp = g_s + rowbase * KEXP;

    for (int g = 0; g < CHUNK / TG; ++g) {
        #pragma unroll 2
        for (int tt = 0; tt < TG; ++tt) {
            const int t = g * TG + tt;
            float iv = ip[(size_t)t * DIM];
            float4 e0 = *(const float4*)(ep + t * KEXP);
            float4 e1 = *(const float4*)(ep + t * KEXP + 4);
            float4 s0 = *(const float4*)(sp + t * KEXP);
            float4 s1 = *(const float4*)(sp + t * KEXP + 4);
            float ev[KEXP] = {e0.x, e0.y, e0.z, e0.w, e1.x, e1.y, e1.z, e1.w};
            float sv[KEXP] = {s0.x, s0.y, s0.z, s0.w, s1.x, s1.y, s1.z, s1.w};
            float y0 = 0.0f, y1 = 0.0f;
            #pragma unroll
            for (int k = 0; k < KEXP; k += 2) {
                m[k]     = fmaf(o[k],     m[k],     ev[k]     * iv);
                m[k + 1] = fmaf(o[k + 1], m[k + 1], ev[k + 1] * iv);
                y0 = fmaf(sv[k],     m[k],     y0);
                y1 = fmaf(sv[k + 1], m[k + 1], y1);
            }
            const float y = y0 + y1;
            ybuf[tt][d] = y;
            float s1r = y, s2r = y * y;
            #pragma unroll
            for (int off = 16; off > 0; off >>= 1) {
                s1r += __shfl_xor_sync(0xFFFFFFFFu, s1r, off);
                s2r += __shfl_xor_sync(0xFFFFFFFFu, s2r, off);
            }
            if (lane == 0) { psum[tt][warp] = s1r; psq[tt][warp] = s2r; }
        }
        __syncthreads();

        // warp w reduces timestep tt=w (16 warps, 16 timesteps)
        {
            float s1r = (lane < 16) ? psum[warp][lane] : 0.0f;
            float s2r = (lane < 16) ? psq[warp][lane] : 0.0f;
            #pragma unroll
            for (int off = 8; off > 0; off >>= 1) {
                s1r += __shfl_xor_sync(0xFFFFFFFFu, s1r, off);
                s2r += __shfl_xor_sync(0xFFFFFFFFu, s2r, off);
            }
            if (lane == 0) {
                const float mu = s1r * (1.0f / DIM);
                const float var = s2r * (1.0f / DIM) - mu * mu;
                smu[warp] = mu;
                srstd[warp] = rsqrtf(var + LN_EPS);
            }
        }
        __syncthreads();

        #pragma unroll 4
        for (int tt = 0; tt < TG; ++tt) {
            const size_t row = rowbase + g * TG + tt;
            const float rv = fmaf((ybuf[tt][d] - smu[tt]) * srstd[tt], gam, bet);
            __half h, l;
            split_half(rv, h, l);
            g_yhi[row * DIM + d] = h;
            g_ylo[row * DIM + d] = l;
        }
        __syncthreads();
    }
}

// ---------------------------------------------------------------------------
// Launch
// ---------------------------------------------------------------------------
extern "C" void kernel_launch(void* const* d_in, const int* in_sizes, int n_in,
                              void* d_out, int out_size) {
    const float* x       = (const float*)d_in[0];
    const float* W_i     = (const float*)d_in[1];
    const float* W_e     = (const float*)d_in[2];
    const float* W_s     = (const float*)d_in[3];
    const float* o_param = (const float*)d_in[4];
    const float* gamma   = (const float*)d_in[5];
    const float* beta    = (const float*)d_in[6];
    const float* W_out   = (const float*)d_in[7];
    float* out = (float*)d_out;

    convert_x_kernel<<<ROWS * DIM / 4 / 256, 256>>>(x);
    convert_w_kernel<<<dim3(16, 16, 2), dim3(32, 8)>>>(W_i, W_out);
    convert_wes_kernel<<<1, 256>>>(W_e, W_s);
    gemm1_kernel<<<dim3(4, 128), 256>>>();
    es_mma_kernel<<<128, 128>>>();
    scan_local_kernel<<<dim3(NCHUNK, BATCH), DIM>>>(o_param);
    scan_prefix_kernel<<<dim3(BATCH, KEXP / 2), DIM>>>(o_param);
    scan_apply_ln_kernel<<<dim3(NCHUNK, BATCH), DIM>>>(o_param, gamma, beta);
    gemm2_kernel<<<dim3(4, 128), 256>>>(out);
}

// round 6
// speedup vs baseline: 2.5028x; 1.0654x over previous
#include <cuda_runtime.h>
#include <cuda_fp16.h>
#include <math.h>
#include <cstdint>

// Problem constants
#define BATCH 4
#define SEQ   4096
#define DIM   512
#define KEXP  8
#define ROWS  (BATCH*SEQ)        // 16384 token rows
#define CHUNK 128                // scan chunk length
#define NCHUNK (SEQ/CHUNK)       // 32 chunks
#define INV_TAU (1.0f/16.0f)
#define LN_EPS 1e-5f

// ---------------------------------------------------------------------------
// Scratch (static device globals)
// ---------------------------------------------------------------------------
__device__ float g_i[ROWS * DIM];                       // x @ W_i (fp32)
__device__ float g_e[ROWS * KEXP];
__device__ float g_s[ROWS * KEXP];
__device__ float g_S[BATCH * NCHUNK * KEXP * DIM];
__device__ float g_P[BATCH * NCHUNK * KEXP * DIM];
__device__ __half g_xhi[ROWS * DIM];
__device__ __half g_xlo[ROWS * DIM];
__device__ __half g_yhi[ROWS * DIM];
__device__ __half g_ylo[ROWS * DIM];
__device__ __half g_wi[DIM * DIM];                      // W_i^T  [N,K] fp16
__device__ __half g_wo[DIM * DIM];                      // W_out^T [N,K] fp16
__device__ __half g_wes[16 * DIM];                      // [W_e|W_s]^T [16,K] fp16

__device__ __forceinline__ void split_half(float v, __half& h, __half& l) {
    h = __float2half(v);
    l = __float2half(v - __half2float(h));
}

// ---------------------------------------------------------------------------
// PTX primitives (baseline sm_80+ — legal for compute_103 PTX target)
// ---------------------------------------------------------------------------
__device__ __forceinline__ uint32_t smem_to_u32(const void* p) {
    uint32_t a;
    asm("{ .reg .u64 t; cvta.to.shared.u64 t, %1; cvt.u32.u64 %0, t; }" : "=r"(a) : "l"(p));
    return a;
}

__device__ __forceinline__ void cp16(uint32_t dst, const void* src) {
    asm volatile("cp.async.cg.shared.global [%0], [%1], 16;" :: "r"(dst), "l"(src));
}
__device__ __forceinline__ void cp_commit() {
    asm volatile("cp.async.commit_group;" ::: "memory");
}
template <int N>
__device__ __forceinline__ void cp_wait() {
    asm volatile("cp.async.wait_group %0;" :: "n"(N) : "memory");
}

__device__ __forceinline__ void ldsm4(uint32_t* r, uint32_t addr) {
    asm volatile("ldmatrix.sync.aligned.m8n8.x4.shared.b16 {%0,%1,%2,%3}, [%4];"
                 : "=r"(r[0]), "=r"(r[1]), "=r"(r[2]), "=r"(r[3]) : "r"(addr));
}

__device__ __forceinline__ void mma16816(float* c, const uint32_t* a, const uint32_t* b) {
    asm volatile(
        "mma.sync.aligned.m16n8k16.row.col.f32.f16.f16.f32 "
        "{%0,%1,%2,%3}, {%4,%5,%6,%7}, {%8,%9}, {%0,%1,%2,%3};"
        : "+f"(c[0]), "+f"(c[1]), "+f"(c[2]), "+f"(c[3])
        : "r"(a[0]), "r"(a[1]), "r"(a[2]), "r"(a[3]), "r"(b[0]), "r"(b[1]));
}

// Swizzle for 32B rows packed into 128B groups: XOR bits[4:5] with bits[7:8]
__device__ __forceinline__ uint32_t sw32(uint32_t off) {
    return off ^ (((off >> 7) & 3u) << 4);
}

// ---------------------------------------------------------------------------
// HMMA 2-term fp16 GEMM: C[Mx512] = (Ahi+Alo) * B^T
// A: hi/lo fp16 [M,512] row-major; B: fp16 [512,512] = W^T, [N,K] row-major
// CTA tile 128(M)x128(N), BK=16, 8 warps of 32x64.
// 4-stage cp.async ring, ONE __syncthreads per k-iter.
// ---------------------------------------------------------------------------
#define NKI (DIM/16)             // 32 k-iterations
#define TILE_B 4096              // bytes per tile (128 rows x 32B)
#define GSTAGES 4

struct __align__(128) GemmSmem { char buf[GSTAGES][3][TILE_B]; };  // 48 KB

__device__ __forceinline__ void gemm_load(uint32_t sbase, int stage, int c,
                                          const __half* Ahi, const __half* Alo,
                                          const __half* B,
                                          int row0, int col0, int tid) {
    const int r = tid >> 1;              // 0..127
    const int h = tid & 1;               // 16B half of the 32B row
    const uint32_t soff = sw32((uint32_t)(r * 32 + h * 16));
    const size_t ga = (size_t)(row0 + r) * DIM + c * 16 + h * 8;
    const size_t gb = (size_t)(col0 + r) * DIM + c * 16 + h * 8;
    const uint32_t base = sbase + (uint32_t)(stage * 3 * TILE_B);
    cp16(base + 0 * TILE_B + soff, Ahi + ga);
    cp16(base + 1 * TILE_B + soff, Alo + ga);
    cp16(base + 2 * TILE_B + soff, B + gb);
}

__device__ __forceinline__ void gemm_body(const __half* __restrict__ Ahi,
                                          const __half* __restrict__ Alo,
                                          const __half* __restrict__ B,
                                          float* __restrict__ C) {
    __shared__ GemmSmem sm;
    const uint32_t sbase = smem_to_u32(&sm);
    const int tid = threadIdx.x;
    const int lane = tid & 31;
    const int wid = tid >> 5;
    const int warp_m = wid >> 1;         // 0..3 -> 32-row slice
    const int warp_n = wid & 1;          // 0..1 -> 64-col slice
    const int row0 = blockIdx.y * 128;
    const int col0 = blockIdx.x * 128;

    const int lr = lane & 15;
    const int lc = (lane >> 4) & 1;

    float acc[2][8][4];
    #pragma unroll
    for (int m = 0; m < 2; m++)
        #pragma unroll
        for (int n = 0; n < 8; n++)
            #pragma unroll
            for (int q = 0; q < 4; q++) acc[m][n][q] = 0.0f;

    // Prologue: fill stages 0..2 (one commit group each)
    #pragma unroll
    for (int s = 0; s < GSTAGES - 1; ++s) {
        gemm_load(sbase, s, s, Ahi, Alo, B, row0, col0, tid);
        cp_commit();
    }

    // ldmatrix source addresses (swizzled), loop-invariant
    uint32_t aAddr[2], bAddr[4];
    #pragma unroll
    for (int m = 0; m < 2; m++)
        aAddr[m] = sw32((uint32_t)((warp_m * 32 + m * 16 + lr) * 32 + lc * 16));
    #pragma unroll
    for (int q = 0; q < 4; q++)
        bAddr[q] = sw32((uint32_t)((warp_n * 64 + q * 16 + lr) * 32 + lc * 16));

    for (int c = 0; c < NKI; ++c) {
        cp_wait<GSTAGES - 2>();          // stage c resident
        __syncthreads();                 // all warps done computing stage c-1

        // Refill the slot freed at iter c-1 (stage (c+3)%4 == (c-1)%4)
        if (c + GSTAGES - 1 < NKI)
            gemm_load(sbase, (c + GSTAGES - 1) & (GSTAGES - 1), c + GSTAGES - 1,
                      Ahi, Alo, B, row0, col0, tid);
        cp_commit();                     // uniform one group per iter (may be empty)

        const uint32_t bb = sbase + (uint32_t)((c & (GSTAGES - 1)) * 3 * TILE_B);
        uint32_t a[2][4], b[8][2];

        // B fragments (shared by both combos)
        #pragma unroll
        for (int q = 0; q < 4; q++) {
            uint32_t t4[4];
            ldsm4(t4, bb + 2 * TILE_B + bAddr[q]);
            b[2*q][0] = t4[0]; b[2*q+1][0] = t4[1];
            b[2*q][1] = t4[2]; b[2*q+1][1] = t4[3];
        }

        // combo 1: Ahi x B
        ldsm4(a[0], bb + 0 * TILE_B + aAddr[0]);
        ldsm4(a[1], bb + 0 * TILE_B + aAddr[1]);
        #pragma unroll
        for (int m = 0; m < 2; m++)
            #pragma unroll
            for (int n = 0; n < 8; n++) mma16816(acc[m][n], a[m], b[n]);

        // combo 2: Alo x B
        ldsm4(a[0], bb + 1 * TILE_B + aAddr[0]);
        ldsm4(a[1], bb + 1 * TILE_B + aAddr[1]);
        #pragma unroll
        for (int m = 0; m < 2; m++)
            #pragma unroll
            for (int n = 0; n < 8; n++) mma16816(acc[m][n], a[m], b[n]);
    }

    // Epilogue (regs only; no smem reuse, so no final barrier needed)
    const int tr = lane >> 2;
    const int tc = (lane & 3) * 2;
    #pragma unroll
    for (int m = 0; m < 2; m++) {
        const int rbase = row0 + warp_m * 32 + m * 16 + tr;
        #pragma unroll
        for (int n = 0; n < 8; n++) {
            const int col = col0 + warp_n * 64 + n * 8 + tc;
            float* p0 = C + (size_t)rbase * DIM + col;
            float* p1 = C + (size_t)(rbase + 8) * DIM + col;
            *(float2*)p0 = make_float2(acc[m][n][0], acc[m][n][1]);
            *(float2*)p1 = make_float2(acc[m][n][2], acc[m][n][3]);
        }
    }
}

__global__ __launch_bounds__(256, 2) void gemm1_kernel() {
    gemm_body(g_xhi, g_xlo, g_wi, g_i);
}
__global__ __launch_bounds__(256, 2) void gemm2_kernel(float* __restrict__ out) {
    gemm_body(g_yhi, g_ylo, g_wo, out);
}

// ---------------------------------------------------------------------------
// es via HMMA: [e|s][Mx16] = (xhi+xlo) * Wes^T.  Wes^T fp16 [16,512] in SMEM.
// CTA: 128 threads (4 warps), 128 rows. Warp: 32 rows (2 m-tiles) x 16 cols.
// 3-stage cp.async ring, one sync per iter. ES_PITCH in halves (>512): 520.
// ---------------------------------------------------------------------------
#define ES_PITCH 520
#define ESTAGES 3

struct __align__(128) EsSmem {
    char abuf[ESTAGES][2][TILE_B];   // 24 KB
    __half w[16 * ES_PITCH];         // 16640 B
};

__device__ __forceinline__ void es_load(uint32_t sbase, int stage, int c,
                                        int row0, int r) {
    #pragma unroll
    for (int j = 0; j < 4; ++j) {
        const int tile = j >> 1, h = j & 1;
        const __half* src = tile ? g_xlo : g_xhi;
        cp16(sbase + (uint32_t)((stage * 2 + tile) * TILE_B)
                   + sw32((uint32_t)(r * 32 + h * 16)),
             src + (size_t)(row0 + r) * DIM + c * 16 + h * 8);
    }
}

__global__ __launch_bounds__(128, 3) void es_mma_kernel() {
    __shared__ EsSmem sm;
    const uint32_t sbase = smem_to_u32(&sm);
    const uint32_t wbase = smem_to_u32(sm.w);
    const int tid = threadIdx.x;
    const int lane = tid & 31;
    const int wid = tid >> 5;            // 0..3
    const int row0 = blockIdx.x * 128;
    const int r = tid;                   // 128 rows, 1 per thread

    // Fill W smem: 16 rows x 512 halves, pitch ES_PITCH halves
    {
        const int row = tid >> 3;              // 0..15
        const int colb = (tid & 7) * 64;       // 0..448
        #pragma unroll
        for (int q = 0; q < 8; ++q) {
            uint4 v = *(const uint4*)(g_wes + row * DIM + colb + q * 8);
            *(uint4*)(sm.w + row * ES_PITCH + colb + q * 8) = v;
        }
    }

    // Prologue: stages 0..1
    #pragma unroll
    for (int s = 0; s < ESTAGES - 1; ++s) {
        es_load(sbase, s, s, row0, r);
        cp_commit();
    }

    const int lr = lane & 15;
    const int lc = (lane >> 4) & 1;
    uint32_t aAddr[2];
    #pragma unroll
    for (int m = 0; m < 2; m++)
        aAddr[m] = sw32((uint32_t)((wid * 32 + m * 16 + lr) * 32 + lc * 16));

    float acc[2][2][4];
    #pragma unroll
    for (int m = 0; m < 2; m++)
        #pragma unroll
        for (int n = 0; n < 2; n++)
            #pragma unroll
            for (int q = 0; q < 4; q++) acc[m][n][q] = 0.0f;

    for (int c = 0; c < NKI; ++c) {
        cp_wait<ESTAGES - 2>();
        __syncthreads();                 // also covers initial W-fill visibility

        if (c + ESTAGES - 1 < NKI) {
            int st = (c + ESTAGES - 1) % ESTAGES;
            es_load(sbase, st, c + ESTAGES - 1, row0, r);
        }
        cp_commit();

        // B fragments from W smem (direct LDS.32, skewed pitch)
        uint32_t b[2][2];
        #pragma unroll
        for (int nt = 0; nt < 2; ++nt) {
            const uint32_t base = wbase
                + (uint32_t)(((nt * 8 + (lane >> 2)) * ES_PITCH + c * 16 + (lane & 3) * 2) * 2);
            asm volatile("ld.shared.b32 %0, [%1];" : "=r"(b[nt][0]) : "r"(base));
            asm volatile("ld.shared.b32 %0, [%1];" : "=r"(b[nt][1]) : "r"(base + 16));
        }

        const uint32_t ab = sbase + (uint32_t)((c % ESTAGES) * 2 * TILE_B);
        uint32_t a[4];
        // combo 1: xhi
        #pragma unroll
        for (int m = 0; m < 2; m++) {
            ldsm4(a, ab + aAddr[m]);
            mma16816(acc[m][0], a, b[0]);
            mma16816(acc[m][1], a, b[1]);
        }
        // combo 2: xlo
        #pragma unroll
        for (int m = 0; m < 2; m++) {
            ldsm4(a, ab + TILE_B + aAddr[m]);
            mma16816(acc[m][0], a, b[0]);
            mma16816(acc[m][1], a, b[1]);
        }
    }

    // Epilogue: nt0 -> e, nt1 -> s
    const int tr = lane >> 2;
    const int tc = (lane & 3) * 2;
    #pragma unroll
    for (int m = 0; m < 2; m++) {
        const int rbase = row0 + wid * 32 + m * 16 + tr;
        #pragma unroll
        for (int nt = 0; nt < 2; nt++) {
            float* dst = nt ? g_s : g_e;
            *(float2*)(dst + (size_t)rbase * KEXP + tc) =
                make_float2(acc[m][nt][0], acc[m][nt][1]);
            *(float2*)(dst + (size_t)(rbase + 8) * KEXP + tc) =
                make_float2(acc[m][nt][2], acc[m][nt][3]);
        }
    }
}

// ---------------------------------------------------------------------------
// Conversions
// ---------------------------------------------------------------------------
__global__ __launch_bounds__(256) void convert_x_kernel(const float* __restrict__ x) {
    const size_t i = (size_t)blockIdx.x * 256 + threadIdx.x;   // float4 index
    float4 v = ((const float4*)x)[i];
    __half h[4], l[4];
    split_half(v.x, h[0], l[0]);
    split_half(v.y, h[1], l[1]);
    split_half(v.z, h[2], l[2]);
    split_half(v.w, h[3], l[3]);
    ((uint2*)g_xhi)[i] = *(uint2*)h;
    ((uint2*)g_xlo)[i] = *(uint2*)l;
}

__global__ __launch_bounds__(256) void convert_w_kernel(const float* __restrict__ W_i,
                                                        const float* __restrict__ W_out) {
    __shared__ float t[32][33];
    const int z = blockIdx.z;
    const float* W = z ? W_out : W_i;
    __half* D = z ? g_wo : g_wi;
    const int n0 = blockIdx.x * 32, k0 = blockIdx.y * 32;
    const int tx = threadIdx.x, ty = threadIdx.y;
    #pragma unroll
    for (int j = 0; j < 4; ++j)
        t[ty + j * 8][tx] = W[(size_t)(k0 + ty + j * 8) * DIM + n0 + tx];
    __syncthreads();
    #pragma unroll
    for (int j = 0; j < 4; ++j) {
        const int nn = ty + j * 8;
        D[(size_t)(n0 + nn) * DIM + k0 + tx] = __float2half(t[tx][nn]);
    }
}

__global__ __launch_bounds__(256) void convert_wes_kernel(const float* __restrict__ W_e,
                                                          const float* __restrict__ W_s) {
    for (int e = threadIdx.x; e < 16 * DIM; e += 256) {
        const int j = e >> 9, d = e & 511;
        const float v = (j < 8) ? W_e[d * KEXP + j] : W_s[d * KEXP + j - 8];
        g_wes[e] = __float2half(v);
    }
}

// ---------------------------------------------------------------------------
// Decay helper
// ---------------------------------------------------------------------------
__device__ __forceinline__ void load_decay(const float* __restrict__ o_param,
                                           int d, float scale, float o[KEXP]) {
    #pragma unroll
    for (int k = 0; k < KEXP; k++) {
        float op = o_param[k * DIM + d];
        float ls = fminf(op, 0.0f) - log1pf(expf(-fabsf(op)));
        o[k] = expf(ls * scale);
    }
}

// ---------------------------------------------------------------------------
// Scan phase 1: per-chunk local end state
// ---------------------------------------------------------------------------
__global__ __launch_bounds__(DIM) void scan_local_kernel(const float* __restrict__ o_param) {
    const int c = blockIdx.x, b = blockIdx.y, d = threadIdx.x;
    float o[KEXP], m[KEXP];
    load_decay(o_param, d, INV_TAU, o);
    #pragma unroll
    for (int k = 0; k < KEXP; k++) m[k] = 0.0f;

    const int t0 = c * CHUNK;
    const float* ip = g_i + ((size_t)b * SEQ + t0) * DIM + d;
    const float* ep = g_e + ((size_t)b * SEQ + t0) * KEXP;

    #pragma unroll 2
    for (int t = 0; t < CHUNK; t++) {
        float iv = ip[(size_t)t * DIM];
        float4 e0 = *(const float4*)(ep + t * KEXP);
        float4 e1 = *(const float4*)(ep + t * KEXP + 4);
        float ev[KEXP] = {e0.x, e0.y, e0.z, e0.w, e1.x, e1.y, e1.z, e1.w};
        #pragma unroll
        for (int k = 0; k < KEXP; k++)
            m[k] = fmaf(o[k], m[k], ev[k] * iv);
    }
    #pragma unroll
    for (int k = 0; k < KEXP; k++)
        g_S[(((size_t)b * NCHUNK + c) * KEXP + k) * DIM + d] = m[k];
}

// ---------------------------------------------------------------------------
// Scan phase 2: prefix over chunks; loads hoisted for MLP.
// ---------------------------------------------------------------------------
__global__ __launch_bounds__(DIM) void scan_prefix_kernel(const float* __restrict__ o_param) {
    const int b = blockIdx.x;
    const int kp = blockIdx.y * 2;
    const int d = threadIdx.x;

    float oL0, oL1;
    {
        float op0 = o_param[kp * DIM + d];
        float op1 = o_param[(kp + 1) * DIM + d];
        float ls0 = fminf(op0, 0.0f) - log1pf(expf(-fabsf(op0)));
        float ls1 = fminf(op1, 0.0f) - log1pf(expf(-fabsf(op1)));
        oL0 = expf(ls0 * (INV_TAU * (float)CHUNK));
        oL1 = expf(ls1 * (INV_TAU * (float)CHUNK));
    }

    float s0[NCHUNK], s1[NCHUNK];
    #pragma unroll
    for (int c = 0; c < NCHUNK; c++) {
        s0[c] = g_S[(((size_t)b * NCHUNK + c) * KEXP + kp) * DIM + d];
        s1[c] = g_S[(((size_t)b * NCHUNK + c) * KEXP + kp + 1) * DIM + d];
    }
    float p0 = 0.0f, p1 = 0.0f;
    #pragma unroll
    for (int c = 0; c < NCHUNK; c++) {
        g_P[(((size_t)b * NCHUNK + c) * KEXP + kp) * DIM + d] = p0;
        g_P[(((size_t)b * NCHUNK + c) * KEXP + kp + 1) * DIM + d] = p1;
        p0 = fmaf(oL0, p0, s0[c]);
        p1 = fmaf(oL1, p1, s1[c]);
    }
}

// ---------------------------------------------------------------------------
// Scan phase 3 + LayerNorm fused: replay chunk, block-reduce LN over d=512,
// emit fp16 hi/lo directly. grid (NCHUNK, BATCH), block 512, 16 warps.
// ---------------------------------------------------------------------------
#define TG 16   // timesteps buffered per group

__global__ __launch_bounds__(DIM) void scan_apply_ln_kernel(const float* __restrict__ o_param,
                                                            const float* __restrict__ gamma,
                                                            const float* __restrict__ beta) {
    __shared__ float ybuf[TG][DIM];
    __shared__ float psum[TG][16];
    __shared__ float psq[TG][16];
    __shared__ float smu[TG], srstd[TG];

    const int c = blockIdx.x, b = blockIdx.y, d = threadIdx.x;
    const int lane = d & 31, warp = d >> 5;

    float o[KEXP], m[KEXP];
    load_decay(o_param, d, INV_TAU, o);
    #pragma unroll
    for (int k = 0; k < KEXP; k++)
        m[k] = g_P[(((size_t)b * NCHUNK + c) * KEXP + k) * DIM + d];

    const float gam = gamma[d];
    const float bet = beta[d];

    const int t0 = c * CHUNK;
    const size_t rowbase = (size_t)b * SEQ + t0;
    const float* ip = g_i + rowbase * DIM + d;
    const float* ep = g_e + rowbase * KEXP;
    const float* sp = g_s + rowbase * KEXP;

    for (int g = 0; g < CHUNK / TG; ++g) {
        #pragma unroll 2
        for (int tt = 0; tt < TG; ++tt) {
            const int t = g * TG + tt;
            float iv = ip[(size_t)t * DIM];
            float4 e0 = *(const float4*)(ep + t * KEXP);
            float4 e1 = *(const float4*)(ep + t * KEXP + 4);
            float4 s0 = *(const float4*)(sp + t * KEXP);
            float4 s1 = *(const float4*)(sp + t * KEXP + 4);
            float ev[KEXP] = {e0.x, e0.y, e0.z, e0.w, e1.x, e1.y, e1.z, e1.w};
            float sv[KEXP] = {s0.x, s0.y, s0.z, s0.w, s1.x, s1.y, s1.z, s1.w};
            float y0 = 0.0f, y1 = 0.0f;
            #pragma unroll
            for (int k = 0; k < KEXP; k += 2) {
                m[k]     = fmaf(o[k],     m[k],     ev[k]     * iv);
                m[k + 1] = fmaf(o[k + 1], m[k + 1], ev[k + 1] * iv);
                y0 = fmaf(sv[k],     m[k],     y0);
                y1 = fmaf(sv[k + 1], m[k + 1], y1);
            }
            const float y = y0 + y1;
            ybuf[tt][d] = y;
            float s1r = y, s2r = y * y;
            #pragma unroll
            for (int off = 16; off > 0; off >>= 1) {
                s1r += __shfl_xor_sync(0xFFFFFFFFu, s1r, off);
                s2r += __shfl_xor_sync(0xFFFFFFFFu, s2r, off);
            }
            if (lane == 0) { psum[tt][warp] = s1r; psq[tt][warp] = s2r; }
        }
        __syncthreads();

        // warp w reduces timestep tt=w (16 warps, 16 timesteps)
        {
            float s1r = (lane < 16) ? psum[warp][lane] : 0.0f;
            float s2r = (lane < 16) ? psq[warp][lane] : 0.0f;
            #pragma unroll
            for (int off = 8; off > 0; off >>= 1) {
                s1r += __shfl_xor_sync(0xFFFFFFFFu, s1r, off);
                s2r += __shfl_xor_sync(0xFFFFFFFFu, s2r, off);
            }
            if (lane == 0) {
                const float mu = s1r * (1.0f / DIM);
                const float var = s2r * (1.0f / DIM) - mu * mu;
                smu[warp] = mu;
                srstd[warp] = rsqrtf(var + LN_EPS);
            }
        }
        __syncthreads();

        #pragma unroll 4
        for (int tt = 0; tt < TG; ++tt) {
            const size_t row = rowbase + g * TG + tt;
            const float rv = fmaf((ybuf[tt][d] - smu[tt]) * srstd[tt], gam, bet);
            __half h, l;
            split_half(rv, h, l);
            g_yhi[row * DIM + d] = h;
            g_ylo[row * DIM + d] = l;
        }
        __syncthreads();
    }
}

// ---------------------------------------------------------------------------
// Launch
// ---------------------------------------------------------------------------
extern "C" void kernel_launch(void* const* d_in, const int* in_sizes, int n_in,
                              void* d_out, int out_size) {
    const float* x       = (const float*)d_in[0];
    const float* W_i     = (const float*)d_in[1];
    const float* W_e     = (const float*)d_in[2];
    const float* W_s     = (const float*)d_in[3];
    const float* o_param = (const float*)d_in[4];
    const float* gamma   = (const float*)d_in[5];
    const float* beta    = (const float*)d_in[6];
    const float* W_out   = (const float*)d_in[7];
    float* out = (float*)d_out;

    convert_x_kernel<<<ROWS * DIM / 4 / 256, 256>>>(x);
    convert_w_kernel<<<dim3(16, 16, 2), dim3(32, 8)>>>(W_i, W_out);
    convert_wes_kernel<<<1, 256>>>(W_e, W_s);
    gemm1_kernel<<<dim3(4, 128), 256>>>();
    es_mma_kernel<<<128, 128>>>();
    scan_local_kernel<<<dim3(NCHUNK, BATCH), DIM>>>(o_param);
    scan_prefix_kernel<<<dim3(BATCH, KEXP / 2), DIM>>>(o_param);
    scan_apply_ln_kernel<<<dim3(NCHUNK, BATCH), DIM>>>(o_param, gamma, beta);
    gemm2_kernel<<<dim3(4, 128), 256>>>(out);
}